// round 12
// baseline (speedup 1.0000x reference)
#include <cuda_runtime.h>
#include <math.h>
#include <stdint.h>

#define NB 256
#define NCH 256
#define ROI 7
#define NITEMS (NB * 32)     // 8192 work items: (roi, 8-channel group)
#define GRIDX (148 * 8)      // one full occupancy wave (8 blocks/SM @ 32 regs)

static __device__ __forceinline__ float neginf() {
    return __int_as_float(0xff800000);
}

// RN(1/7): XLA rewrites divide-by-constant into multiply-by-reciprocal.
// This MUST stay a multiply (bit-exactness depends on it).
#define R7 (1.0f / 7.0f)

// ---------- grouped path: lanes = (pw-bin, within-bin column) ----------
template <int W>
static __device__ __forceinline__ void pool_grouped(
    const float* __restrict__ ftp, float* __restrict__ out,
    const int2* s_h, const int2* s_w, const int* s_g,
    int roi, int c, int img, int lane)
{
    int b = 0;
    #pragma unroll
    for (int q = 1; q < 7; ++q) b += (lane >= s_g[q]) ? 1 : 0;
    const int  total = s_g[7];
    const int  d     = lane - s_g[b];
    const int2 wb    = s_w[b];
    const int  cntR  = wb.y - wb.x;        // real bin width (0 => empty)
    const int  eR    = cntR - d;           // remaining cols in my segment
    const bool writer = (d == 0) && (lane < total);
    const int  col   = min(wb.x + ((lane < total) ? d : 0), W - 1);

    const float* base = ftp + (size_t)(img * NCH + c) * (size_t)(W * W) + col;
    float* op = out + ((size_t)roi * NCH + c) * (ROI * ROI) + b;

    #pragma unroll
    for (int ph = 0; ph < ROI; ++ph) {
        const int2 hb   = s_h[ph];
        const int nrows = hb.y - hb.x;                 // warp-uniform, <= 6
        const float* a  = base + hb.x * W;             // W compile-time

        float v0 = neginf(), v1 = neginf(), v2 = neginf();
        float v3 = neginf(), v4 = neginf(), v5 = neginf();
        if (nrows > 0) v0 = __ldg(a);
        if (nrows > 1) v1 = __ldg(a + W);
        if (nrows > 2) v2 = __ldg(a + 2 * W);
        if (nrows > 3) v3 = __ldg(a + 3 * W);
        if (nrows > 4) v4 = __ldg(a + 4 * W);
        if (nrows > 5) v5 = __ldg(a + 5 * W);
        float m = fmaxf(fmaxf(fmaxf(v0, v1), fmaxf(v2, v3)), fmaxf(v4, v5));

        // segmented suffix-max tree: 3 shfl_down, predicate keeps segments clean
        float t;
        t = __shfl_down_sync(0xffffffffu, m, 1); if (1 < eR) m = fmaxf(m, t);
        t = __shfl_down_sync(0xffffffffu, m, 2); if (2 < eR) m = fmaxf(m, t);
        t = __shfl_down_sync(0xffffffffu, m, 4); if (4 < eR) m = fmaxf(m, t);

        if (writer) {
            const bool empty = (nrows <= 0) || (cntR <= 0);
            *op = empty ? 0.0f : m;
        }
        op += ROI;
    }
}

// ---------- fallback path (rare: wide ROIs), runtime W ----------
static __device__ __forceinline__ void pool_fallback(
    const float* __restrict__ ftp, float* __restrict__ out,
    const int2* s_h, const int2* s_w, int W,
    int roi, int c, int img, int wbase, int lane)
{
    const int col = wbase + lane;
    const bool cv = col < s_w[6].y;
    const float* base = ftp + (size_t)(img * NCH + c) * (size_t)(W * W) + col;

    const int pw   = (lane < 7) ? lane : 0;
    const int2 wb  = s_w[pw];
    const int cnt  = wb.y - wb.x;
    const int src0 = wb.x - wbase;

    float* op = out + ((size_t)roi * NCH + c) * (ROI * ROI) + pw;

    #pragma unroll
    for (int ph = 0; ph < ROI; ++ph) {
        const int2 hb   = s_h[ph];
        const int nrows = hb.y - hb.x;
        const float* a  = base + hb.x * W;

        float v0 = neginf(), v1 = neginf(), v2 = neginf();
        float v3 = neginf(), v4 = neginf(), v5 = neginf();
        if (cv & (nrows > 0)) v0 = __ldg(a);
        if (cv & (nrows > 1)) v1 = __ldg(a + W);
        if (cv & (nrows > 2)) v2 = __ldg(a + 2 * W);
        if (cv & (nrows > 3)) v3 = __ldg(a + 3 * W);
        if (cv & (nrows > 4)) v4 = __ldg(a + 4 * W);
        if (cv & (nrows > 5)) v5 = __ldg(a + 5 * W);
        const float cm = fmaxf(fmaxf(fmaxf(v0, v1), fmaxf(v2, v3)), fmaxf(v4, v5));

        float m = __shfl_sync(0xffffffffu, cm, src0);
        #pragma unroll
        for (int k = 1; k < 6; ++k) {
            const float v = __shfl_sync(0xffffffffu, cm, src0 + k);
            if (k < cnt) m = fmaxf(m, v);
        }

        if (lane < 7) {
            const bool empty = (nrows <= 0) || (cnt <= 0);
            *op = empty ? 0.0f : m;
        }
        op += ROI;
    }
}

__global__ __launch_bounds__(256, 8) void roi_pool_fast(
    const float* __restrict__ ft0, const float* __restrict__ ft1,
    const float* __restrict__ ft2, const float* __restrict__ ft3,
    const float* __restrict__ rois, const int* __restrict__ roi_idx,
    float* __restrict__ out)
{
    // double-buffered per-item descriptors
    __shared__ int2 s_h[2][8], s_w[2][8];
    __shared__ int  s_g[2][8];     // group starts; [7] = total
    __shared__ int  s_hdr[2][6];   // W, level, img, wbase, grouped?

    const int wid  = threadIdx.x >> 5;
    const int lane = threadIdx.x & 31;
    const int tid  = threadIdx.x;

    // ---- descriptor builder for one item's ROI into buffer bb (threads 0..7) ----
    auto compute_desc = [&](int roi, int bb) {
        const float y1 = rois[roi * 4 + 0];
        const float x1 = rois[roi * 4 + 1];
        const float y2 = rois[roi * 4 + 2];
        const float x2 = rois[roi * 4 + 3];

        // level = clip(floor(4+log2(bsz/224)),2,5)-2 == thresholds 112/224/448
        const float bsz = __fsqrt_rn(__fmul_rn(__fadd_rn(y2, -y1), __fadd_rn(x2, -x1)));
        const int l = (bsz >= 112.0f ? 1 : 0) + (bsz >= 224.0f ? 1 : 0) +
                      (bsz >= 448.0f ? 1 : 0);
        const int H = 200 >> l;                         // 200,100,50,25
        const float scale = 0.25f / (float)(1 << l);    // exact powers of two

        const int sh = (int)floorf(__fadd_rn(__fmul_rn(y1, scale), 0.5f));
        const int sw = (int)floorf(__fadd_rn(__fmul_rn(x1, scale), 0.5f));
        const int eh = (int)floorf(__fadd_rn(__fmul_rn(y2, scale), 0.5f));
        const int ew = (int)floorf(__fadd_rn(__fmul_rn(x2, scale), 0.5f));
        const float bh = __fmul_rn((float)max(eh - sh + 1, 1), R7);
        const float bw = __fmul_rn((float)max(ew - sw + 1, 1), R7);

        const int p = tid;                // p=7 fills unused slot 7 (harmless)
        const float pf = (float)p;
        int2 hb, wb;
        hb.x = min(max((int)floorf(__fmul_rn(pf, bh)) + sh, 0), H);
        hb.y = min(max((int)ceilf(__fmul_rn(__fadd_rn(pf, 1.0f), bh)) + sh, 0), H);
        wb.x = min(max((int)floorf(__fmul_rn(pf, bw)) + sw, 0), H);
        wb.y = min(max((int)ceilf(__fmul_rn(__fadd_rn(pf, 1.0f), bw)) + sw, 0), H);
        s_h[bb][p] = hb;
        s_w[bb][p] = wb;
        if (tid == 0) {
            s_hdr[bb][0] = H;
            s_hdr[bb][1] = l;
            s_hdr[bb][2] = roi_idx[roi];
            s_hdr[bb][3] = min(max(sw, 0), H);   // wbase (fallback path)
        }
        __syncwarp(0xffu);
        if (tid == 0) {
            int g = 0;
            #pragma unroll
            for (int q = 0; q < 7; ++q) {
                s_g[bb][q] = g;
                g += max(s_w[bb][q].y - s_w[bb][q].x, 1);   // empty bins get 1 slot
            }
            s_g[bb][7] = g;
            s_hdr[bb][4] = (g <= 32) ? 1 : 0;
        }
    };

    int item = blockIdx.x;
    int cur  = 0;

    if (tid < 8) compute_desc(item >> 5, 0);
    __syncthreads();

    // persistent loop: ~7 items per block, prologue of next item overlapped
    while (item < NITEMS) {
        const int next = item + GRIDX;
        if ((tid < 8) && (next < NITEMS)) compute_desc(next >> 5, cur ^ 1);

        const int roi = item >> 5;
        const int c   = ((item & 31) << 3) + wid;
        const int lvl = s_hdr[cur][1];
        const int img = s_hdr[cur][2];

        if (s_hdr[cur][4]) {
            switch (lvl) {
                case 0:  pool_grouped<200>(ft0, out, s_h[cur], s_w[cur], s_g[cur], roi, c, img, lane); break;
                case 1:  pool_grouped<100>(ft1, out, s_h[cur], s_w[cur], s_g[cur], roi, c, img, lane); break;
                case 2:  pool_grouped<50> (ft2, out, s_h[cur], s_w[cur], s_g[cur], roi, c, img, lane); break;
                default: pool_grouped<25> (ft3, out, s_h[cur], s_w[cur], s_g[cur], roi, c, img, lane); break;
            }
        } else {
            const float* ftp = (lvl == 0) ? ft0 : (lvl == 1) ? ft1 : (lvl == 2) ? ft2 : ft3;
            pool_fallback(ftp, out, s_h[cur], s_w[cur], s_hdr[cur][0],
                          roi, c, img, s_hdr[cur][3], lane);
        }

        __syncthreads();   // next buffer complete; this buffer free for reuse
        item = next;
        cur ^= 1;
    }
}

extern "C" void kernel_launch(void* const* d_in, const int* in_sizes, int n_in,
                              void* d_out, int out_size) {
    const float* ft0 = 0; const float* ft1 = 0; const float* ft2 = 0;
    const float* ft3 = 0; const float* rois = 0; const int* roi_idx = 0;
    for (int i = 0; i < n_in; ++i) {
        switch (in_sizes[i]) {
            case 2 * 256 * 200 * 200: ft0 = (const float*)d_in[i]; break;
            case 2 * 256 * 100 * 100: ft1 = (const float*)d_in[i]; break;
            case 2 * 256 * 50 * 50:   ft2 = (const float*)d_in[i]; break;
            case 2 * 256 * 25 * 25:   ft3 = (const float*)d_in[i]; break;
            case 256 * 4:             rois = (const float*)d_in[i]; break;
            case 256:                 roi_idx = (const int*)d_in[i]; break;
        }
    }
    float* out = (float*)d_out;

    // persistent: one occupancy wave, each block grid-strides over items
    roi_pool_fast<<<GRIDX, 256>>>(ft0, ft1, ft2, ft3, rois, roi_idx, out);
}

// round 13
// speedup vs baseline: 1.2941x; 1.2941x over previous
#include <cuda_runtime.h>
#include <math.h>
#include <stdint.h>

#define NB 256
#define NCH 256
#define ROI 7

static __device__ __forceinline__ float neginf() {
    return __int_as_float(0xff800000);
}

// RN(1/7): XLA rewrites divide-by-constant into multiply-by-reciprocal.
// This MUST stay a multiply (bit-exactness depends on it).
#define R7 (1.0f / 7.0f)

template <int W>
static __device__ __forceinline__ void pool_body(
    const float* __restrict__ ftp, float* __restrict__ out,
    const int2* s_h, const int2* s_w,
    int roi, int c, int img, int wbase, int lane)
{
    const int col = wbase + lane;
    const bool cv = col < s_w[6].y;        // per-lane column validity
    const float* base = ftp + (size_t)(img * NCH + c) * (size_t)(W * W) + col;

    // lane-resident pw-bin data (lanes 0..6 are output columns)
    const int pw   = (lane < 7) ? lane : 0;
    const int2 wb  = s_w[pw];
    const int cnt  = wb.y - wb.x;          // <= 6
    const int src0 = wb.x - wbase;         // >= 0, <= 24

    float* op = out + ((size_t)roi * NCH + c) * (ROI * ROI) + pw;

    #pragma unroll
    for (int ph = 0; ph < ROI; ++ph) {
        const int2 hb   = s_h[ph];
        const int nrows = hb.y - hb.x;                 // warp-uniform, <= 6
        const float* a  = base + hb.x * W;             // W is compile-time

        // flat predicates (warp-uniform row count AND per-lane column validity);
        // masked lanes contribute no L1 sectors/wavefronts, no branches emitted
        float v0 = neginf(), v1 = neginf(), v2 = neginf();
        float v3 = neginf(), v4 = neginf(), v5 = neginf();
        if (cv & (nrows > 0)) v0 = __ldg(a);
        if (cv & (nrows > 1)) v1 = __ldg(a + W);
        if (cv & (nrows > 2)) v2 = __ldg(a + 2 * W);
        if (cv & (nrows > 3)) v3 = __ldg(a + 3 * W);
        if (cv & (nrows > 4)) v4 = __ldg(a + 4 * W);
        if (cv & (nrows > 5)) v5 = __ldg(a + 5 * W);
        const float cm = fmaxf(fmaxf(fmaxf(v0, v1), fmaxf(v2, v3)), fmaxf(v4, v5));

        // segment max over lanes [src0, src0+cnt): fixed 6 unconditional SHFLs,
        // predicated FMNMX only (no control flow)
        float m = __shfl_sync(0xffffffffu, cm, src0);
        #pragma unroll
        for (int k = 1; k < 6; ++k) {
            const float v = __shfl_sync(0xffffffffu, cm, src0 + k);
            if (k < cnt) m = fmaxf(m, v);
        }

        if (lane < 7) {
            const bool empty = (nrows <= 0) || (cnt <= 0);
            *op = empty ? 0.0f : m;
        }
        op += ROI;
    }
}

__global__ __launch_bounds__(256, 8) void roi_pool_fast(
    const float* __restrict__ ft0, const float* __restrict__ ft1,
    const float* __restrict__ ft2, const float* __restrict__ ft3,
    const float* __restrict__ rois, const int* __restrict__ roi_idx,
    float* __restrict__ out)
{
    __shared__ int2 s_h[8], s_w[8];
    __shared__ int  s_hdr[4];   // W, level, img, wbase

    // CHANNEL-MAJOR swizzle: concurrent blocks = all 256 ROIs in the SAME
    // channel slice -> overlapping ROI windows share L2 lines (working set
    // ~few MB << L2), duplicate fetches hit L2 (234cyc) instead of DRAM (577+)
    const int roi  = blockIdx.x & 255;
    const int cg   = (blockIdx.x >> 8) << 3;   // block's base channel
    const int wid  = threadIdx.x >> 5;
    const int lane = threadIdx.x & 31;
    const int tid  = threadIdx.x;

    // ---- per-ROI scalar math, once per block (threads 0..7) ----
    if (tid < 8) {
        const float y1 = rois[roi * 4 + 0];
        const float x1 = rois[roi * 4 + 1];
        const float y2 = rois[roi * 4 + 2];
        const float x2 = rois[roi * 4 + 3];

        // level = clip(floor(4+log2(bsz/224)),2,5)-2 == thresholds 112/224/448
        const float bsz = __fsqrt_rn(__fmul_rn(__fadd_rn(y2, -y1), __fadd_rn(x2, -x1)));
        const int l = (bsz >= 112.0f ? 1 : 0) + (bsz >= 224.0f ? 1 : 0) +
                      (bsz >= 448.0f ? 1 : 0);
        const int H = 200 >> l;                         // 200,100,50,25
        const float scale = 0.25f / (float)(1 << l);    // exact powers of two

        const int sh = (int)floorf(__fadd_rn(__fmul_rn(y1, scale), 0.5f));
        const int sw = (int)floorf(__fadd_rn(__fmul_rn(x1, scale), 0.5f));
        const int eh = (int)floorf(__fadd_rn(__fmul_rn(y2, scale), 0.5f));
        const int ew = (int)floorf(__fadd_rn(__fmul_rn(x2, scale), 0.5f));
        const float bh = __fmul_rn((float)max(eh - sh + 1, 1), R7);
        const float bw = __fmul_rn((float)max(ew - sw + 1, 1), R7);

        const int p = tid;                // p=7 fills unused slot 7 (harmless)
        const float pf = (float)p;
        int2 hb, wb;
        hb.x = min(max((int)floorf(__fmul_rn(pf, bh)) + sh, 0), H);
        hb.y = min(max((int)ceilf(__fmul_rn(__fadd_rn(pf, 1.0f), bh)) + sh, 0), H);
        wb.x = min(max((int)floorf(__fmul_rn(pf, bw)) + sw, 0), H);
        wb.y = min(max((int)ceilf(__fmul_rn(__fadd_rn(pf, 1.0f), bw)) + sw, 0), H);
        s_h[p] = hb;
        s_w[p] = wb;
        if (tid == 0) {
            s_hdr[0] = H;
            s_hdr[1] = l;
            s_hdr[2] = roi_idx[roi];
            s_hdr[3] = min(max(sw, 0), H);   // wbase
        }
    }
    __syncthreads();

    const int lvl   = s_hdr[1];
    const int img   = s_hdr[2];
    const int wbase = s_hdr[3];
    const int c     = cg + wid;

    // per-block uniform dispatch to the compile-time-W body
    switch (lvl) {
        case 0:  pool_body<200>(ft0, out, s_h, s_w, roi, c, img, wbase, lane); break;
        case 1:  pool_body<100>(ft1, out, s_h, s_w, roi, c, img, wbase, lane); break;
        case 2:  pool_body<50> (ft2, out, s_h, s_w, roi, c, img, wbase, lane); break;
        default: pool_body<25> (ft3, out, s_h, s_w, roi, c, img, wbase, lane); break;
    }
}

extern "C" void kernel_launch(void* const* d_in, const int* in_sizes, int n_in,
                              void* d_out, int out_size) {
    const float* ft0 = 0; const float* ft1 = 0; const float* ft2 = 0;
    const float* ft3 = 0; const float* rois = 0; const int* roi_idx = 0;
    for (int i = 0; i < n_in; ++i) {
        switch (in_sizes[i]) {
            case 2 * 256 * 200 * 200: ft0 = (const float*)d_in[i]; break;
            case 2 * 256 * 100 * 100: ft1 = (const float*)d_in[i]; break;
            case 2 * 256 * 50 * 50:   ft2 = (const float*)d_in[i]; break;
            case 2 * 256 * 25 * 25:   ft3 = (const float*)d_in[i]; break;
            case 256 * 4:             rois = (const float*)d_in[i]; break;
            case 256:                 roi_idx = (const int*)d_in[i]; break;
        }
    }
    float* out = (float*)d_out;

    // block = 8 warps = 8 channels of one ROI; channel-major block ordering
    roi_pool_fast<<<NB * 32, 256>>>(ft0, ft1, ft2, ft3, rois, roi_idx, out);
}